// round 8
// baseline (speedup 1.0000x reference)
#include <cuda_runtime.h>
#include <math.h>

#define BB    2
#define NQQ   900
#define EE    256
#define NH    8
#define HDIM  32
#define HWK   4096
#define RPEH  512
#define LOG2E_F 1.4426950408889634f
#define QSCALE_F 0.17677669529663687f

// Scratch. g_qT padded: attn reads past row end on the last query tile.
__device__ float g_qT[BB * NH * HDIM * NQQ + 1024]; // [(b*8+h)*32+d][900]
__device__ float g_kT[BB * NH * HDIM * HWK];        // [(b*8+h)*32+d][4096]
__device__ float g_v [BB * HWK * EE];
__device__ float g_rx[BB * NH * NQQ * 64];          // [bh][q][w], *log2e
__device__ float g_ryT[BB * NH * 64 * NQQ];         // [bh][c][q]
__device__ float g_att[BB * NQQ * EE];

typedef unsigned long long u64;

__device__ __forceinline__ float fexp2(float x) {
    float y; asm("ex2.approx.ftz.f32 %0, %1;" : "=f"(y) : "f"(x)); return y;
}
__device__ __forceinline__ u64 ffma2(u64 a, u64 b, u64 c) {
    u64 d; asm("fma.rn.f32x2 %0, %1, %2, %3;" : "=l"(d) : "l"(a), "l"(b), "l"(c)); return d;
}
__device__ __forceinline__ u64 fmul2(u64 a, u64 b) {
    u64 d; asm("mul.rn.f32x2 %0, %1, %2;" : "=l"(d) : "l"(a), "l"(b)); return d;
}
__device__ __forceinline__ u64 fadd2(u64 a, u64 b) {
    u64 d; asm("add.rn.f32x2 %0, %1, %2;" : "=l"(d) : "l"(a), "l"(b)); return d;
}
__device__ __forceinline__ u64 dup2(float x) {
    u64 r; asm("mov.b64 %0, {%1, %1};" : "=l"(r) : "f"(x)); return r;
}
__device__ __forceinline__ u64 pack2(float lo, float hi) {
    u64 r; asm("mov.b64 %0, {%1, %2};" : "=l"(r) : "f"(lo), "f"(hi)); return r;
}
__device__ __forceinline__ float2 unpk2(u64 v) {
    float2 r; asm("mov.b64 {%0, %1}, %2;" : "=f"(r.x), "=f"(r.y) : "l"(v)); return r;
}
__device__ __forceinline__ float logdelta(float d) {
    float l = log2f(fabsf(d) + 1.0f) * (1.0f / 3.0f);
    return copysignf(l, d);
}

// ---------------------------------------------------------------------------
// C = alpha*(A[M,256] @ W[256,256] + bias).  TMODE 0: row-major.
// TMODE 1: per-head transposed: C[((m/plane)*8 + n/32)*32 + n%32][m%plane]
// ---------------------------------------------------------------------------
template<int TMODE>
__global__ void gemm_bias_kernel(const float* __restrict__ A,
                                 const float* __restrict__ Wm,
                                 const float* __restrict__ bias,
                                 float* __restrict__ C,
                                 int M, int plane, float alpha)
{
    __shared__ __align__(16) float As[16][64];
    __shared__ __align__(16) float Ws[16][64];

    int tid = threadIdx.x;
    int m0 = blockIdx.x * 64;
    int n0 = blockIdx.y * 64;
    int tm = tid >> 4, tn = tid & 15;
    int lrow = tid >> 2, lkq = tid & 3;
    int wkk = tid >> 4, wnq = tid & 15;

    u64 acc2[4][2] = {};

    for (int k0 = 0; k0 < 256; k0 += 16) {
        float4 av = make_float4(0.f, 0.f, 0.f, 0.f);
        int m = m0 + lrow;
        if (m < M) av = *(const float4*)&A[m * 256 + k0 + 4 * lkq];
        As[4 * lkq + 0][lrow] = av.x;
        As[4 * lkq + 1][lrow] = av.y;
        As[4 * lkq + 2][lrow] = av.z;
        As[4 * lkq + 3][lrow] = av.w;
        *(float4*)&Ws[wkk][4 * wnq] =
            *(const float4*)&Wm[(k0 + wkk) * 256 + n0 + 4 * wnq];
        __syncthreads();

        #pragma unroll
        for (int kk = 0; kk < 16; kk++) {
            float4 a = *(const float4*)&As[kk][4 * tm];
            ulonglong2 w = *(const ulonglong2*)&Ws[kk][4 * tn];
            float ar[4] = {a.x, a.y, a.z, a.w};
            #pragma unroll
            for (int i = 0; i < 4; i++) {
                u64 ad = dup2(ar[i]);
                acc2[i][0] = ffma2(ad, w.x, acc2[i][0]);
                acc2[i][1] = ffma2(ad, w.y, acc2[i][1]);
            }
        }
        __syncthreads();
    }

    float4 bv = *(const float4*)&bias[n0 + 4 * tn];
    float o[4][4];
    #pragma unroll
    for (int i = 0; i < 4; i++) {
        float2 lo = unpk2(acc2[i][0]);
        float2 hi = unpk2(acc2[i][1]);
        o[i][0] = alpha * (lo.x + bv.x);
        o[i][1] = alpha * (lo.y + bv.y);
        o[i][2] = alpha * (hi.x + bv.z);
        o[i][3] = alpha * (hi.y + bv.w);
    }

    if (TMODE == 0) {
        #pragma unroll
        for (int i = 0; i < 4; i++) {
            int m = m0 + 4 * tm + i;
            if (m < M)
                *(float4*)&C[m * 256 + n0 + 4 * tn] =
                    make_float4(o[i][0], o[i][1], o[i][2], o[i][3]);
        }
    } else {
        __shared__ float Ts[64][65];
        #pragma unroll
        for (int i = 0; i < 4; i++)
            #pragma unroll
            for (int j = 0; j < 4; j++)
                Ts[4 * tn + j][4 * tm + i] = o[i][j];
        __syncthreads();
        for (int idx = tid; idx < 4096; idx += 256) {
            int ml = idx & 63, nl = idx >> 6;
            int m = m0 + ml;
            if (m < M) {
                int bq = m / plane;
                int mm = m - bq * plane;
                int n = n0 + nl;
                int row = (bq * NH + (n >> 5)) * 32 + (n & 31);
                C[(long long)row * plane + mm] = Ts[nl][ml];
            }
        }
    }
}

// ---------------------------------------------------------------------------
// RPE MLP, axis-split: grid (225, 2); blockIdx.y = axis (0=x, 1=y).
// 256 threads = 8 (b,q) x 32 lanes; 2 positions per thread.
// ---------------------------------------------------------------------------
__global__ void rpe_kernel(const float* __restrict__ refp,
                           const float* __restrict__ W1x, const float* __restrict__ b1x,
                           const float* __restrict__ W2x,
                           const float* __restrict__ W1y, const float* __restrict__ b1y,
                           const float* __restrict__ W2y)
{
    __shared__ __align__(16) float2 sW1[RPEH];
    __shared__ __align__(16) float sb1[RPEH];
    __shared__ __align__(16) float sW2[RPEH * 8];

    int tid = threadIdx.x;
    int axis = blockIdx.y;
    const float* W1 = axis ? W1y : W1x;
    const float* b1 = axis ? b1y : b1x;
    const float* W2 = axis ? W2y : W2x;

    for (int i = tid; i < RPEH; i += 256) {
        sW1[i] = make_float2(W1[i], W1[RPEH + i]);
        sb1[i] = b1[i];
    }
    for (int i = tid; i < RPEH * 8; i += 256)
        sW2[i] = W2[i];
    __syncthreads();

    int bq = blockIdx.x * 8 + (tid >> 5);
    int b = bq / NQQ, q = bq - b * NQQ;
    float4 r = *(const float4*)&refp[bq * 4];
    int lane = tid & 31;

    float ctr = axis ? r.y : r.x;
    float sz  = axis ? r.w : r.z;
    float lo = (ctr - 0.5f * sz) * 1024.0f;
    float hi = (ctr + 0.5f * sz) * 1024.0f;
    float posA = (lane + 0.5f) * 16.0f;
    float posB = (lane + 32.5f) * 16.0f;
    float d1a = logdelta(lo - posA), d2a = logdelta(hi - posA);
    float d1b = logdelta(lo - posB), d2b = logdelta(hi - posB);

    u64 a0[4] = {}, a1[4] = {};
    #pragma unroll 4
    for (int hh = 0; hh < RPEH; hh++) {
        float2 w = sW1[hh];
        float bvf = sb1[hh];
        float v0 = fmaxf(fmaf(d1a, w.x, fmaf(d2a, w.y, bvf)), 0.0f);
        float v1 = fmaxf(fmaf(d1b, w.x, fmaf(d2b, w.y, bvf)), 0.0f);
        u64 v0d = dup2(v0), v1d = dup2(v1);
        ulonglong2 wlo = *(const ulonglong2*)&sW2[hh * 8];
        ulonglong2 whi = *(const ulonglong2*)&sW2[hh * 8 + 4];
        a0[0] = ffma2(v0d, wlo.x, a0[0]);  a0[1] = ffma2(v0d, wlo.y, a0[1]);
        a0[2] = ffma2(v0d, whi.x, a0[2]);  a0[3] = ffma2(v0d, whi.y, a0[3]);
        a1[0] = ffma2(v1d, wlo.x, a1[0]);  a1[1] = ffma2(v1d, wlo.y, a1[1]);
        a1[2] = ffma2(v1d, whi.x, a1[2]);  a1[3] = ffma2(v1d, whi.y, a1[3]);
    }

    float o0[8], o1[8];
    #pragma unroll
    for (int c = 0; c < 4; c++) {
        float2 x0 = unpk2(a0[c]); float2 x1 = unpk2(a1[c]);
        o0[2*c] = x0.x * LOG2E_F;  o0[2*c+1] = x0.y * LOG2E_F;
        o1[2*c] = x1.x * LOG2E_F;  o1[2*c+1] = x1.y * LOG2E_F;
    }
    long long bh = (long long)b * NH;
    #pragma unroll
    for (int hd = 0; hd < 8; hd++) {
        if (axis == 0) {
            g_rx[((bh + hd) * NQQ + q) * 64 + lane]      = o0[hd];
            g_rx[((bh + hd) * NQQ + q) * 64 + lane + 32] = o1[hd];
        } else {
            g_ryT[((bh + hd) * 64 + lane)      * NQQ + q] = o0[hd];
            g_ryT[((bh + hd) * 64 + lane + 32) * NQQ + q] = o1[hd];
        }
    }
}

// ---------------------------------------------------------------------------
// Fused attention v3: grid (15 qtiles x 8 heads x 2 batch), 256 threads.
// qtile=64, chunk=64 keys (one grid row). Thread tile: GEMM1 4q x 4k,
// GEMM2 4q x 2d. K/V pre-duplicated in smem (no MOV dup in hot loops).
// Interleaved key groups: group g = keys {g, g+16, g+32, g+48} + swizzled
// Kd offsets => conflict-free K load/store, P store, rx load.
// Register softmax, shfl over 16-lane k-group. 2 barriers/chunk.
// ---------------------------------------------------------------------------
#define OFF_K   2048                 // Kd: [32][140]
#define OFF_V   6528                 // Vd: 2 x [64][72]
#define OFF_S   15744                // ST: [64][68]
#define OFF_RX  20096                // rxT: [64][68]
#define OFF_RY  24448                // ryc: 2 x [64]
#define ATTN_SMF 24576               // floats (96 KB)

__global__ void __launch_bounds__(256, 2) attn_kernel(float* __restrict__ outp)
{
    extern __shared__ __align__(16) float sm[];
    float* QsT = sm;             // [32 d][64 q]
    float* Kd  = sm + OFF_K;
    float* Vd  = sm + OFF_V;
    float* ST  = sm + OFF_S;
    float* rxT = sm + OFF_RX;
    float* ryc = sm + OFF_RY;

    int tid = threadIdx.x;
    int qt = blockIdx.x, h = blockIdx.y, b = blockIdx.z;
    int q0 = qt * 64;
    int tq = tid >> 4, tk = tid & 15;
    int q0t = tq * 4;
    int koff = tk * 8 + (tk >> 2) * 4;
    long long bh = (long long)b * NH + h;
    const float* kbp = g_kT + bh * 32 * HWK;
    const float* vbp = g_v + (long long)b * HWK * EE + h * HDIM;
    const float* ryp = g_ryT + bh * 64 * NQQ;

    // loader mappings
    int kd_ = tid >> 3, kg2 = tid & 7;          // K: d row, key-group pair
    int vk = tid >> 2, vs = (tid & 3) * 8;      // V: key row, d segment
    int ryq = min(q0 + (tid & 63), NQQ - 1);

    // ---- Q fill ----
    {
        const float* qb = g_qT + bh * 32 * NQQ;
        int d = tid >> 3, q8 = (tid & 7) * 8;
        float4 a0 = *(const float4*)&qb[d * NQQ + q0 + q8];
        float4 a1 = *(const float4*)&qb[d * NQQ + q0 + q8 + 4];
        *(float4*)&QsT[d * 64 + q8] = a0;
        *(float4*)&QsT[d * 64 + q8 + 4] = a1;
    }
    // ---- rx fill: [w][q] with pad 68 ----
    {
        const float* rxb = g_rx + bh * NQQ * 64;
        for (int idx = tid; idx < 64 * 16; idx += 256) {
            int q = idx >> 4, w4 = (idx & 15) * 4;
            int qg = min(q0 + q, NQQ - 1);
            float4 v = *(const float4*)&rxb[qg * 64 + w4];
            rxT[(w4 + 0) * 68 + q] = v.x;
            rxT[(w4 + 1) * 68 + q] = v.y;
            rxT[(w4 + 2) * 68 + q] = v.z;
            rxT[(w4 + 3) * 68 + q] = v.w;
        }
    }
    // ---- prologue: chunk 0 ----
    {
        float2 kr[4];
        #pragma unroll
        for (int s = 0; s < 4; s++)
            kr[s] = *(const float2*)&kbp[kd_ * HWK + 2 * kg2 + 16 * s];
        float4 v0 = *(const float4*)&vbp[vk * EE + vs];
        float4 v1 = *(const float4*)&vbp[vk * EE + vs + 4];
        int off = kd_ * 140 + kg2 * 16 + (kg2 >> 1) * 4;
        *(float4*)&Kd[off]      = make_float4(kr[0].x, kr[0].x, kr[1].x, kr[1].x);
        *(float4*)&Kd[off + 4]  = make_float4(kr[2].x, kr[2].x, kr[3].x, kr[3].x);
        *(float4*)&Kd[off + 8]  = make_float4(kr[0].y, kr[0].y, kr[1].y, kr[1].y);
        *(float4*)&Kd[off + 12] = make_float4(kr[2].y, kr[2].y, kr[3].y, kr[3].y);
        int voff = vk * 72 + vs * 2;
        *(float4*)&Vd[voff]      = make_float4(v0.x, v0.x, v0.y, v0.y);
        *(float4*)&Vd[voff + 4]  = make_float4(v0.z, v0.z, v0.w, v0.w);
        *(float4*)&Vd[voff + 8]  = make_float4(v1.x, v1.x, v1.y, v1.y);
        *(float4*)&Vd[voff + 12] = make_float4(v1.z, v1.z, v1.w, v1.w);
        if (tid < 64) ryc[tid] = ryp[ryq];
    }
    __syncthreads();

    float m_prev[4], l_acc[4];
    #pragma unroll
    for (int r = 0; r < 4; r++) { m_prev[r] = -1e30f; l_acc[r] = 0.0f; }
    u64 o2[2][2] = {};

    #pragma unroll 1
    for (int ch = 0; ch < 64; ch++) {
        int buf = ch & 1;
        const float* Vc = Vd + buf * (64 * 72);

        // prefetch next chunk (LDG early; STS after barrier 1)
        float2 kr[4]; float4 vr0, vr1; float ryr = 0.0f;
        if (ch < 63) {
            int k0n = (ch + 1) * 64;
            #pragma unroll
            for (int s = 0; s < 4; s++)
                kr[s] = *(const float2*)&kbp[kd_ * HWK + k0n + 2 * kg2 + 16 * s];
            vr0 = *(const float4*)&vbp[(k0n + vk) * EE + vs];
            vr1 = *(const float4*)&vbp[(k0n + vk) * EE + vs + 4];
            if (tid < 64) ryr = ryp[(ch + 1) * NQQ + ryq];
        }

        // ---- GEMM1: 4q x 4k, acc pairs along q ----
        u64 s2[2][4] = {};
        #pragma unroll 8
        for (int kk = 0; kk < 32; kk++) {
            ulonglong2 qv = *(const ulonglong2*)&QsT[kk * 64 + q0t];
            const float* kp = &Kd[kk * 140 + koff];
            ulonglong2 ka = *(const ulonglong2*)kp;
            ulonglong2 kb2 = *(const ulonglong2*)(kp + 4);
            s2[0][0] = ffma2(qv.x, ka.x, s2[0][0]);
            s2[1][0] = ffma2(qv.y, ka.x, s2[1][0]);
            s2[0][1] = ffma2(qv.x, ka.y, s2[0][1]);
            s2[1][1] = ffma2(qv.y, ka.y, s2[1][1]);
            s2[0][2] = ffma2(qv.x, kb2.x, s2[0][2]);
            s2[1][2] = ffma2(qv.y, kb2.x, s2[1][2]);
            s2[0][3] = ffma2(qv.x, kb2.y, s2[0][3]);
            s2[1][3] = ffma2(qv.y, kb2.y, s2[1][3]);
        }

        // ---- bias: + ry[q] + rx[q][w], w = tk + 16j ----
        {
            ulonglong2 ryu = *(const ulonglong2*)&ryc[buf * 64 + q0t];
            #pragma unroll
            for (int j = 0; j < 4; j++) {
                int w = tk + 16 * j;
                ulonglong2 ru = *(const ulonglong2*)&rxT[w * 68 + q0t];
                s2[0][j] = fadd2(s2[0][j], fadd2(ru.x, ryu.x));
                s2[1][j] = fadd2(s2[1][j], fadd2(ru.y, ryu.y));
            }
        }

        // ---- register softmax (rows = 4 q, cols across 16 tk lanes) ----
        float s[4][4];
        #pragma unroll
        for (int i = 0; i < 2; i++)
            #pragma unroll
            for (int j = 0; j < 4; j++) {
                float2 v = unpk2(s2[i][j]);
                s[2 * i][j] = v.x;
                s[2 * i + 1][j] = v.y;
            }
        float mx[4], sum[4], scl[4];
        #pragma unroll
        for (int r = 0; r < 4; r++)
            mx[r] = fmaxf(fmaxf(s[r][0], s[r][1]), fmaxf(s[r][2], s[r][3]));
        #pragma unroll
        for (int d = 1; d < 16; d <<= 1)
            #pragma unroll
            for (int r = 0; r < 4; r++)
                mx[r] = fmaxf(mx[r], __shfl_xor_sync(0xffffffffu, mx[r], d));
        #pragma unroll
        for (int r = 0; r < 4; r++) {
            float mn = fmaxf(m_prev[r], mx[r]);
            float p0 = fexp2(s[r][0] - mn);
            float p1 = fexp2(s[r][1] - mn);
            float p2 = fexp2(s[r][2] - mn);
            float p3 = fexp2(s[r][3] - mn);
            s[r][0] = p0; s[r][1] = p1; s[r][2] = p2; s[r][3] = p3;
            sum[r] = (p0 + p1) + (p2 + p3);
            scl[r] = fexp2(m_prev[r] - mn);
            m_prev[r] = mn;
        }
        #pragma unroll
        for (int d = 1; d < 16; d <<= 1)
            #pragma unroll
            for (int r = 0; r < 4; r++)
                sum[r] += __shfl_xor_sync(0xffffffffu, sum[r], d);
        #pragma unroll
        for (int r = 0; r < 4; r++)
            l_acc[r] = l_acc[r] * scl[r] + sum[r];

        // ---- P store: ST[k][q], k = tk + 16j (conflict-free) ----
        #pragma unroll
        for (int j = 0; j < 4; j++) {
            int k = tk + 16 * j;
            *(float4*)&ST[k * 68 + q0t] =
                make_float4(s[0][j], s[1][j], s[2][j], s[3][j]);
        }
        __syncthreads();

        // ---- store prefetched chunk ----
        if (ch < 63) {
            int off = kd_ * 140 + kg2 * 16 + (kg2 >> 1) * 4;
            *(float4*)&Kd[off]      = make_float4(kr[0].x, kr[0].x, kr[1].x, kr[1].x);
            *(float4*)&Kd[off + 4]  = make_float4(kr[2].x, kr[2].x, kr[3].x, kr[3].x);
            *(float4*)&Kd[off + 8]  = make_float4(kr[0].y, kr[0].y, kr[1].y, kr[1].y);
            *(float4*)&Kd[off + 12] = make_float4(kr[2].y, kr[2].y, kr[3].y, kr[3].y);
            float* Vn = Vd + (buf ^ 1) * (64 * 72);
            int voff = vk * 72 + vs * 2;
            *(float4*)&Vn[voff]      = make_float4(vr0.x, vr0.x, vr0.y, vr0.y);
            *(float4*)&Vn[voff + 4]  = make_float4(vr0.z, vr0.z, vr0.w, vr0.w);
            *(float4*)&Vn[voff + 8]  = make_float4(vr1.x, vr1.x, vr1.y, vr1.y);
            *(float4*)&Vn[voff + 12] = make_float4(vr1.z, vr1.z, vr1.w, vr1.w);
            if (tid < 64) ryc[(buf ^ 1) * 64 + tid] = ryr;
        }

        // ---- GEMM2: 4q x 2d, acc pairs along q, V dup'd ----
        {
            o2[0][0] = fmul2(o2[0][0], pack2(scl[0], scl[1]));
            o2[0][1] = fmul2(o2[0][1], pack2(scl[0], scl[1]));
            o2[1][0] = fmul2(o2[1][0], pack2(scl[2], scl[3]));
            o2[1][1] = fmul2(o2[1][1], pack2(scl[2], scl[3]));
            #pragma unroll 8
            for (int kk = 0; kk < 64; kk++) {
                ulonglong2 pp = *(const ulonglong2*)&ST[kk * 68 + q0t];
                ulonglong2 vv = *(const ulonglong2*)&Vc[kk * 72 + tk * 4];
                o2[0][0] = ffma2(pp.x, vv.x, o2[0][0]);
                o2[0][1] = ffma2(pp.x, vv.y, o2[0][1]);
                o2[1][0] = ffma2(pp.y, vv.x, o2[1][0]);
                o2[1][1] = ffma2(pp.y, vv.y, o2[1][1]);
            }
        }
        __syncthreads();
    }

    // ---- epilogue: d = 2*tk + {0,1} ----
    #pragma unroll
    for (int r = 0; r < 4; r++) {
        int q = q0 + q0t + r;
        if (q < NQQ) {
            float inv = 1.0f / l_acc[r];
            float2 vd0 = unpk2(o2[r >> 1][0]);
            float2 vd1 = unpk2(o2[r >> 1][1]);
            float a = (r & 1) ? vd0.y : vd0.x;
            float c = (r & 1) ? vd1.y : vd1.x;
            *(float2*)&outp[((long long)b * NQQ + q) * EE + h * HDIM + 2 * tk] =
                make_float2(a * inv, c * inv);
        }
    }
}

// ---------------------------------------------------------------------------
extern "C" void kernel_launch(void* const* d_in, const int* in_sizes, int n_in,
                              void* d_out, int out_size)
{
    const float* query = (const float*)d_in[0];
    const float* key   = (const float*)d_in[1];
    const float* value = (const float*)d_in[2];
    const float* refp  = (const float*)d_in[3];
    const float* Wq = (const float*)d_in[4];  const float* bq = (const float*)d_in[5];
    const float* Wk = (const float*)d_in[6];  const float* bk = (const float*)d_in[7];
    const float* Wv = (const float*)d_in[8];  const float* bv = (const float*)d_in[9];
    const float* Wo = (const float*)d_in[10]; const float* bo = (const float*)d_in[11];
    const float* W1x = (const float*)d_in[12]; const float* b1x = (const float*)d_in[13];
    const float* W2x = (const float*)d_in[14];
    const float* W1y = (const float*)d_in[15]; const float* b1y = (const float*)d_in[16];
    const float* W2y = (const float*)d_in[17];
    float* out = (float*)d_out;

    float *pqT, *pkT, *pv, *patt;
    cudaGetSymbolAddress((void**)&pqT, g_qT);
    cudaGetSymbolAddress((void**)&pkT, g_kT);
    cudaGetSymbolAddress((void**)&pv, g_v);
    cudaGetSymbolAddress((void**)&patt, g_att);

    static int attr_done = 0;
    if (!attr_done) {
        cudaFuncSetAttribute(attn_kernel,
                             cudaFuncAttributeMaxDynamicSharedMemorySize,
                             ATTN_SMF * 4);
        attr_done = 1;
    }

    gemm_bias_kernel<1><<<dim3(29, 4), 256>>>(query, Wq, bq, pqT, BB * NQQ,
                                              NQQ, QSCALE_F * LOG2E_F);
    gemm_bias_kernel<1><<<dim3(128, 4), 256>>>(key, Wk, bk, pkT, BB * HWK,
                                               HWK, 1.0f);
    gemm_bias_kernel<0><<<dim3(128, 4), 256>>>(value, Wv, bv, pv, BB * HWK,
                                               HWK, 1.0f);

    rpe_kernel<<<dim3(225, 2), 256>>>(refp, W1x, b1x, W2x, W1y, b1y, W2y);

    attn_kernel<<<dim3(15, NH, BB), 256, ATTN_SMF * 4>>>(patt);

    gemm_bias_kernel<0><<<dim3(29, 4), 256>>>(patt, Wo, bo, out, BB * NQQ,
                                              NQQ, 1.0f);
}

// round 9
// speedup vs baseline: 1.2281x; 1.2281x over previous
#include <cuda_runtime.h>
#include <math.h>

#define BB    2
#define NQQ   900
#define EE    256
#define NH    8
#define HDIM  32
#define HWK   4096
#define RPEH  512
#define LOG2E_F 1.4426950408889634f
#define QSCALE_F 0.17677669529663687f
#define NSPLIT 2
#define QPAD   960

// Scratch. g_qT padded: attn reads past row end on the last query tile.
__device__ float g_qT[BB * NH * HDIM * NQQ + 1024]; // [(b*8+h)*32+d][900]
__device__ float g_kT[BB * NH * HDIM * HWK];        // [(b*8+h)*32+d][4096]
__device__ float g_v [BB * HWK * EE];
__device__ float g_rx[BB * NH * NQQ * 64];          // [bh][q][w], *log2e
__device__ float g_ryT[BB * NH * 64 * NQQ];         // [bh][c][q]
__device__ float g_att[BB * NQQ * EE];
// split partials: [s][b][h][QPAD][32] and [s][b][h][QPAD]
__device__ float g_po[NSPLIT * BB * NH * QPAD * HDIM];
__device__ float g_pm[NSPLIT * BB * NH * QPAD];
__device__ float g_pl[NSPLIT * BB * NH * QPAD];

typedef unsigned long long u64;

__device__ __forceinline__ float fexp2(float x) {
    float y; asm("ex2.approx.ftz.f32 %0, %1;" : "=f"(y) : "f"(x)); return y;
}
__device__ __forceinline__ u64 ffma2(u64 a, u64 b, u64 c) {
    u64 d; asm("fma.rn.f32x2 %0, %1, %2, %3;" : "=l"(d) : "l"(a), "l"(b), "l"(c)); return d;
}
__device__ __forceinline__ u64 fmul2(u64 a, u64 b) {
    u64 d; asm("mul.rn.f32x2 %0, %1, %2;" : "=l"(d) : "l"(a), "l"(b)); return d;
}
__device__ __forceinline__ u64 dup2(float x) {
    u64 r; asm("mov.b64 %0, {%1, %1};" : "=l"(r) : "f"(x)); return r;
}
__device__ __forceinline__ float2 unpk2(u64 v) {
    float2 r; asm("mov.b64 {%0, %1}, %2;" : "=f"(r.x), "=f"(r.y) : "l"(v)); return r;
}
__device__ __forceinline__ float logdelta(float d) {
    float l = log2f(fabsf(d) + 1.0f) * (1.0f / 3.0f);
    return copysignf(l, d);
}

// ---------------------------------------------------------------------------
// C = alpha*(A[M,256] @ W[256,256] + bias).  TMODE 0: row-major.
// TMODE 1: per-head transposed: C[((m/plane)*8 + n/32)*32 + n%32][m%plane]
// ---------------------------------------------------------------------------
template<int TMODE>
__global__ void gemm_bias_kernel(const float* __restrict__ A,
                                 const float* __restrict__ Wm,
                                 const float* __restrict__ bias,
                                 float* __restrict__ C,
                                 int M, int plane, float alpha)
{
    __shared__ __align__(16) float As[16][64];
    __shared__ __align__(16) float Ws[16][64];

    int tid = threadIdx.x;
    int m0 = blockIdx.x * 64;
    int n0 = blockIdx.y * 64;
    int tm = tid >> 4, tn = tid & 15;
    int lrow = tid >> 2, lkq = tid & 3;
    int wkk = tid >> 4, wnq = tid & 15;

    u64 acc2[4][2] = {};

    for (int k0 = 0; k0 < 256; k0 += 16) {
        float4 av = make_float4(0.f, 0.f, 0.f, 0.f);
        int m = m0 + lrow;
        if (m < M) av = *(const float4*)&A[m * 256 + k0 + 4 * lkq];
        As[4 * lkq + 0][lrow] = av.x;
        As[4 * lkq + 1][lrow] = av.y;
        As[4 * lkq + 2][lrow] = av.z;
        As[4 * lkq + 3][lrow] = av.w;
        *(float4*)&Ws[wkk][4 * wnq] =
            *(const float4*)&Wm[(k0 + wkk) * 256 + n0 + 4 * wnq];
        __syncthreads();

        #pragma unroll
        for (int kk = 0; kk < 16; kk++) {
            float4 a = *(const float4*)&As[kk][4 * tm];
            ulonglong2 w = *(const ulonglong2*)&Ws[kk][4 * tn];
            float ar[4] = {a.x, a.y, a.z, a.w};
            #pragma unroll
            for (int i = 0; i < 4; i++) {
                u64 ad = dup2(ar[i]);
                acc2[i][0] = ffma2(ad, w.x, acc2[i][0]);
                acc2[i][1] = ffma2(ad, w.y, acc2[i][1]);
            }
        }
        __syncthreads();
    }

    float4 bv = *(const float4*)&bias[n0 + 4 * tn];
    float o[4][4];
    #pragma unroll
    for (int i = 0; i < 4; i++) {
        float2 lo = unpk2(acc2[i][0]);
        float2 hi = unpk2(acc2[i][1]);
        o[i][0] = alpha * (lo.x + bv.x);
        o[i][1] = alpha * (lo.y + bv.y);
        o[i][2] = alpha * (hi.x + bv.z);
        o[i][3] = alpha * (hi.y + bv.w);
    }

    if (TMODE == 0) {
        #pragma unroll
        for (int i = 0; i < 4; i++) {
            int m = m0 + 4 * tm + i;
            if (m < M)
                *(float4*)&C[m * 256 + n0 + 4 * tn] =
                    make_float4(o[i][0], o[i][1], o[i][2], o[i][3]);
        }
    } else {
        __shared__ float Ts[64][65];
        #pragma unroll
        for (int i = 0; i < 4; i++)
            #pragma unroll
            for (int j = 0; j < 4; j++)
                Ts[4 * tn + j][4 * tm + i] = o[i][j];
        __syncthreads();
        for (int idx = tid; idx < 4096; idx += 256) {
            int ml = idx & 63, nl = idx >> 6;
            int m = m0 + ml;
            if (m < M) {
                int bq = m / plane;
                int mm = m - bq * plane;
                int n = n0 + nl;
                int row = (bq * NH + (n >> 5)) * 32 + (n & 31);
                C[(long long)row * plane + mm] = Ts[nl][ml];
            }
        }
    }
}

// ---------------------------------------------------------------------------
// RPE MLP, axis-split (R7 version, verified): grid (225, 2), 256 threads.
// ---------------------------------------------------------------------------
__global__ void rpe_kernel(const float* __restrict__ refp,
                           const float* __restrict__ W1x, const float* __restrict__ b1x,
                           const float* __restrict__ W2x,
                           const float* __restrict__ W1y, const float* __restrict__ b1y,
                           const float* __restrict__ W2y)
{
    __shared__ __align__(16) float2 sW1[RPEH];
    __shared__ __align__(16) float sb1[RPEH];
    __shared__ __align__(16) float sW2[RPEH * 8];

    int tid = threadIdx.x;
    int axis = blockIdx.y;
    const float* W1 = axis ? W1y : W1x;
    const float* b1 = axis ? b1y : b1x;
    const float* W2 = axis ? W2y : W2x;

    for (int i = tid; i < RPEH; i += 256) {
        sW1[i] = make_float2(W1[i], W1[RPEH + i]);
        sb1[i] = b1[i];
    }
    for (int i = tid; i < RPEH * 8; i += 256)
        sW2[i] = W2[i];
    __syncthreads();

    int bq = blockIdx.x * 8 + (tid >> 5);
    int b = bq / NQQ, q = bq - b * NQQ;
    float4 r = *(const float4*)&refp[bq * 4];
    int lane = tid & 31;

    float ctr = axis ? r.y : r.x;
    float sz  = axis ? r.w : r.z;
    float lo = (ctr - 0.5f * sz) * 1024.0f;
    float hi = (ctr + 0.5f * sz) * 1024.0f;
    float posA = (lane + 0.5f) * 16.0f;
    float posB = (lane + 32.5f) * 16.0f;
    float d1a = logdelta(lo - posA), d2a = logdelta(hi - posA);
    float d1b = logdelta(lo - posB), d2b = logdelta(hi - posB);

    u64 a0[4] = {}, a1[4] = {};
    #pragma unroll 4
    for (int hh = 0; hh < RPEH; hh++) {
        float2 w = sW1[hh];
        float bvf = sb1[hh];
        float v0 = fmaxf(fmaf(d1a, w.x, fmaf(d2a, w.y, bvf)), 0.0f);
        float v1 = fmaxf(fmaf(d1b, w.x, fmaf(d2b, w.y, bvf)), 0.0f);
        u64 v0d = dup2(v0), v1d = dup2(v1);
        ulonglong2 wlo = *(const ulonglong2*)&sW2[hh * 8];
        ulonglong2 whi = *(const ulonglong2*)&sW2[hh * 8 + 4];
        a0[0] = ffma2(v0d, wlo.x, a0[0]);  a0[1] = ffma2(v0d, wlo.y, a0[1]);
        a0[2] = ffma2(v0d, whi.x, a0[2]);  a0[3] = ffma2(v0d, whi.y, a0[3]);
        a1[0] = ffma2(v1d, wlo.x, a1[0]);  a1[1] = ffma2(v1d, wlo.y, a1[1]);
        a1[2] = ffma2(v1d, whi.x, a1[2]);  a1[3] = ffma2(v1d, whi.y, a1[3]);
    }

    float o0[8], o1[8];
    #pragma unroll
    for (int c = 0; c < 4; c++) {
        float2 x0 = unpk2(a0[c]); float2 x1 = unpk2(a1[c]);
        o0[2*c] = x0.x * LOG2E_F;  o0[2*c+1] = x0.y * LOG2E_F;
        o1[2*c] = x1.x * LOG2E_F;  o1[2*c+1] = x1.y * LOG2E_F;
    }
    long long bh = (long long)b * NH;
    #pragma unroll
    for (int hd = 0; hd < 8; hd++) {
        if (axis == 0) {
            g_rx[((bh + hd) * NQQ + q) * 64 + lane]      = o0[hd];
            g_rx[((bh + hd) * NQQ + q) * 64 + lane + 32] = o1[hd];
        } else {
            g_ryT[((bh + hd) * 64 + lane)      * NQQ + q] = o0[hd];
            g_ryT[((bh + hd) * 64 + lane + 32) * NQQ + q] = o1[hd];
        }
    }
}

// ---------------------------------------------------------------------------
// Fused attention (R4 553us kernel + KV split):
//  grid (15 qtiles, 8 heads, 2 batch * 2 splits), 128 threads, 52 KB smem
//  => 4 blocks/SM capacity, 480 blocks (~3.2/SM resident).
//  Each block handles 64 chunks of 32 keys (2048 keys = half the grid rows)
//  and writes unnormalized (O, m, l) partials; combine_kernel merges.
// ---------------------------------------------------------------------------
#define ATTN_SMEM_FLOATS 12992
__global__ void __launch_bounds__(128, 4) attn_kernel()
{
    extern __shared__ __align__(16) float sm[];
    float* QsT  = sm;            // [32][64]
    float* KsT  = sm + 2048;     // 2 x [32 d][32 k]
    float* Vs   = sm + 4096;     // 2 x [32 k][32 d]
    float* ST   = sm + 6144;     // [32 k][68]
    float* rxsT = sm + 8320;     // [64 w][68]
    float* ryb  = sm + 12672;    // 2 x [64]
    float* mrow = sm + 12800;
    float* lrow = sm + 12864;
    float* srow = sm + 12928;

    int tid = threadIdx.x;
    int qt = blockIdx.x, h = blockIdx.y;
    int b = blockIdx.z >> 1, s = blockIdx.z & 1;
    int q0 = qt * 64;
    int tq = tid >> 3, tx = tid & 7;
    long long bh = (long long)b * NH + h;

    if (tid < 64) { mrow[tid] = -1e30f; lrow[tid] = 0.0f; }

    // Q tile: coalesced rows of g_qT, conflict-free stores.
    {
        int q4 = (tid & 15) * 4;
        int dr = tid >> 4;
        const float* qb = g_qT + bh * 32 * NQQ;
        #pragma unroll
        for (int r2 = 0; r2 < 4; r2++) {
            int d = dr + 8 * r2;
            float4 val = make_float4(0.f, 0.f, 0.f, 0.f);
            if (q0 + q4 < NQQ) val = *(const float4*)&qb[d * NQQ + q0 + q4];
            *(float4*)&QsT[d * 64 + q4] = val;
        }
    }
    // rx tile, transposed into [w][q] (pad 68)
    {
        const float* rxb = g_rx + bh * NQQ * 64;
        for (int idx = tid; idx < 64 * 16; idx += 128) {
            int q = idx >> 4, w4 = (idx & 15) * 4;
            int qg = min(q0 + q, NQQ - 1);
            float4 v = *(const float4*)&rxb[qg * 64 + w4];
            rxsT[(w4 + 0) * 68 + q] = v.x;
            rxsT[(w4 + 1) * 68 + q] = v.y;
            rxsT[(w4 + 2) * 68 + q] = v.z;
            rxsT[(w4 + 3) * 68 + q] = v.w;
        }
    }

    int lk4 = (tid & 7) * 4;
    int lr16 = tid >> 3;         // 0..15
    const float* kb = g_kT + bh * 32 * HWK;
    const float* vb = g_v + (long long)b * HWK * EE + h * HDIM;
    const float* ryp = g_ryT + bh * 64 * NQQ;
    int ryq = min(q0 + tid, NQQ - 1);

    int ch0 = s * 64;            // first chunk of this split
    int chN = ch0 + 64;

    // Prologue: first chunk -> buffer 0
    *(float4*)&KsT[lr16 * 32 + lk4]        = *(const float4*)&kb[lr16 * HWK + ch0 * 32 + lk4];
    *(float4*)&KsT[(lr16 + 16) * 32 + lk4] = *(const float4*)&kb[(lr16 + 16) * HWK + ch0 * 32 + lk4];
    *(float4*)&Vs[lr16 * 32 + lk4]         = *(const float4*)&vb[(ch0 * 32 + lr16) * EE + lk4];
    *(float4*)&Vs[(lr16 + 16) * 32 + lk4]  = *(const float4*)&vb[(ch0 * 32 + lr16 + 16) * EE + lk4];
    if (tid < 64) ryb[tid] = ryp[(ch0 >> 1) * NQQ + ryq];
    __syncthreads();

    u64 o2[4][2] = {};

    for (int ch = ch0; ch < chN; ch++) {
        int buf = ch & 1;
        int w0 = buf * 32;
        const float* Kc = KsT + buf * 1024;
        const float* Vc = Vs + buf * 1024;
        const float* ryc = ryb + buf * 64;

        // Prefetch chunk ch+1 into registers
        float4 kr0, kr1, vr0, vr1; float ryr = 0.0f;
        if (ch < chN - 1) {
            int k0n = (ch + 1) * 32;
            kr0 = *(const float4*)&kb[lr16 * HWK + k0n + lk4];
            kr1 = *(const float4*)&kb[(lr16 + 16) * HWK + k0n + lk4];
            vr0 = *(const float4*)&vb[(k0n + lr16) * EE + lk4];
            vr1 = *(const float4*)&vb[(k0n + lr16 + 16) * EE + lk4];
            if (tid < 64)
                ryr = ryp[((ch + 1) >> 1) * NQQ + ryq];
        }

        // GEMM1: S[64q][32k] = Q @ K^T, FFMA2 pairs along k
        u64 s2[4][2] = {};
        #pragma unroll 8
        for (int kk = 0; kk < 32; kk++) {
            float4 qv = *(const float4*)&QsT[kk * 64 + 4 * tq];
            ulonglong2 kp = *(const ulonglong2*)&Kc[kk * 32 + 4 * tx];
            float qr[4] = {qv.x, qv.y, qv.z, qv.w};
            #pragma unroll
            for (int i = 0; i < 4; i++) {
                u64 qd = dup2(qr[i]);
                s2[i][0] = ffma2(qd, kp.x, s2[i][0]);
                s2[i][1] = ffma2(qd, kp.y, s2[i][1]);
            }
        }
        float s[4][4];
        #pragma unroll
        for (int i = 0; i < 4; i++) {
            float2 a = unpk2(s2[i][0]); float2 c = unpk2(s2[i][1]);
            s[i][0] = a.x; s[i][1] = a.y; s[i][2] = c.x; s[i][3] = c.y;
        }
        float ry4[4];
        #pragma unroll
        for (int i = 0; i < 4; i++) ry4[i] = ryc[4 * tq + i];
        #pragma unroll
        for (int j = 0; j < 4; j++) {
            float4 rv = *(const float4*)&rxsT[(w0 + 4 * tx + j) * 68 + 4 * tq];
            float4 sv;
            sv.x = s[0][j] + ry4[0] + rv.x;
            sv.y = s[1][j] + ry4[1] + rv.y;
            sv.z = s[2][j] + ry4[2] + rv.z;
            sv.w = s[3][j] + ry4[3] + rv.w;
            *(float4*)&ST[(4 * tx + j) * 68 + 4 * tq] = sv;
        }
        __syncthreads();

        // Softmax: 2 threads per query
        {
            int q = tid >> 1, hf = tid & 1;
            float mold = mrow[q];
            float mx = mold;
            #pragma unroll
            for (int s5 = 0; s5 < 16; s5++)
                mx = fmaxf(mx, ST[(2 * s5 + hf) * 68 + q]);
            mx = fmaxf(mx, __shfl_xor_sync(0xffffffffu, mx, 1));
            float sum = 0.0f;
            #pragma unroll
            for (int s5 = 0; s5 < 16; s5++) {
                int kk = 2 * s5 + hf;
                float p = fexp2(ST[kk * 68 + q] - mx);
                ST[kk * 68 + q] = p;
                sum += p;
            }
            sum += __shfl_xor_sync(0xffffffffu, sum, 1);
            if (hf == 0) {
                mrow[q] = mx;
                float scl = fexp2(mold - mx);
                lrow[q] = lrow[q] * scl + sum;
                srow[q] = scl;
            }
        }
        __syncthreads();

        // Store prefetched chunk into other buffer
        if (ch < chN - 1) {
            float* Kn = KsT + (buf ^ 1) * 1024;
            float* Vn = Vs + (buf ^ 1) * 1024;
            *(float4*)&Kn[lr16 * 32 + lk4]        = kr0;
            *(float4*)&Kn[(lr16 + 16) * 32 + lk4] = kr1;
            *(float4*)&Vn[lr16 * 32 + lk4]        = vr0;
            *(float4*)&Vn[(lr16 + 16) * 32 + lk4] = vr1;
            if (tid < 64) ryb[(buf ^ 1) * 64 + tid] = ryr;
        }

        // GEMM2: O = scl*O + P @ V, FFMA2 pairs along d
        {
            u64 sc[4];
            #pragma unroll
            for (int i = 0; i < 4; i++) sc[i] = dup2(srow[4 * tq + i]);
            #pragma unroll
            for (int i = 0; i < 4; i++) {
                o2[i][0] = fmul2(o2[i][0], sc[i]);
                o2[i][1] = fmul2(o2[i][1], sc[i]);
            }
            #pragma unroll 8
            for (int kk = 0; kk < 32; kk++) {
                float4 pv = *(const float4*)&ST[kk * 68 + 4 * tq];
                ulonglong2 vp = *(const ulonglong2*)&Vc[kk * 32 + 4 * tx];
                float pr[4] = {pv.x, pv.y, pv.z, pv.w};
                #pragma unroll
                for (int i = 0; i < 4; i++) {
                    u64 pd = dup2(pr[i]);
                    o2[i][0] = ffma2(pd, vp.x, o2[i][0]);
                    o2[i][1] = ffma2(pd, vp.y, o2[i][1]);
                }
            }
        }
        __syncthreads();
    }

    // ---- epilogue: write unnormalized partials + (m, l) ----
    long long po_off = (((long long)s * BB + b) * NH + h) * QPAD * HDIM;
    long long ml_off = (((long long)s * BB + b) * NH + h) * QPAD;
    #pragma unroll
    for (int i = 0; i < 4; i++) {
        int q = q0 + 4 * tq + i;
        if (q < NQQ) {
            float2 lo = unpk2(o2[i][0]);
            float2 hi = unpk2(o2[i][1]);
            *(float4*)&g_po[po_off + (long long)q * HDIM + 4 * tx] =
                make_float4(lo.x, lo.y, hi.x, hi.y);
        }
    }
    if (tid < 64) {
        int q = q0 + tid;
        if (q < NQQ) {
            g_pm[ml_off + q] = mrow[tid];
            g_pl[ml_off + q] = lrow[tid];
        }
    }
}

// ---------------------------------------------------------------------------
// Combine: merge the 2 KV-split partials. 225 blocks x 256 thr x 8 floats.
// ---------------------------------------------------------------------------
__global__ void combine_kernel(float* __restrict__ outp)
{
    const int PS = BB * NH * QPAD * HDIM;   // split stride in g_po
    const int MS = BB * NH * QPAD;          // split stride in g_pm/g_pl
    int t = blockIdx.x * 256 + threadIdx.x;
    int flat = t * 8;
    int b = flat / (NQQ * EE);
    int rem = flat - b * (NQQ * EE);
    int q = rem >> 8;
    int e = rem & 255;
    int h = e >> 5, d = e & 31;
    int po0 = ((b * NH + h) * QPAD + q) * HDIM + d;
    int ml0 = (b * NH + h) * QPAD + q;

    float m0 = g_pm[ml0],      l0 = g_pl[ml0];
    float m1 = g_pm[ml0 + MS], l1 = g_pl[ml0 + MS];
    float m = fmaxf(m0, m1);
    float w0 = fexp2(m0 - m), w1 = fexp2(m1 - m);
    float inv = 1.0f / (l0 * w0 + l1 * w1);

    float4 a0 = *(const float4*)&g_po[po0];
    float4 a1 = *(const float4*)&g_po[po0 + 4];
    float4 c0 = *(const float4*)&g_po[po0 + PS];
    float4 c1 = *(const float4*)&g_po[po0 + PS + 4];

    float4 r0 = make_float4((a0.x * w0 + c0.x * w1) * inv,
                            (a0.y * w0 + c0.y * w1) * inv,
                            (a0.z * w0 + c0.z * w1) * inv,
                            (a0.w * w0 + c0.w * w1) * inv);
    float4 r1 = make_float4((a1.x * w0 + c1.x * w1) * inv,
                            (a1.y * w0 + c1.y * w1) * inv,
                            (a1.z * w0 + c1.z * w1) * inv,
                            (a1.w * w0 + c1.w * w1) * inv);
    *(float4*)&outp[flat] = r0;
    *(float4*)&outp[flat + 4] = r1;
}

// ---------------------------------------------------------------------------
extern "C" void kernel_launch(void* const* d_in, const int* in_sizes, int n_in,
                              void* d_out, int out_size)
{
    const float* query = (const float*)d_in[0];
    const float* key   = (const float*)d_in[1];
    const float* value = (const float*)d_in[2];
    const float* refp  = (const float*)d_in[3];
    const float* Wq = (const float*)d_in[4];  const float* bq = (const float*)d_in[5];
    const float* Wk = (const float*)d_in[6];  const float* bk = (const float*)d_in[7];
    const float* Wv = (const float*)d_in[8];  const float* bv = (const float*)d_in[9];
    const float* Wo = (const float*)d_in[10]; const float* bo = (const float*)d_in[11];
    const float* W1x = (const float*)d_in[12]; const float* b1x = (const float*)d_in[13];
    const float* W2x = (const float*)d_in[14];
    const float* W1y = (const float*)d_in[15]; const float* b1y = (const float*)d_in[16];
    const float* W2y = (const float*)d_in[17];
    float* out = (float*)d_out;

    float *pqT, *pkT, *pv, *patt;
    cudaGetSymbolAddress((void**)&pqT, g_qT);
    cudaGetSymbolAddress((void**)&pkT, g_kT);
    cudaGetSymbolAddress((void**)&pv, g_v);
    cudaGetSymbolAddress((void**)&patt, g_att);

    static int attr_done = 0;
    if (!attr_done) {
        cudaFuncSetAttribute(attn_kernel,
                             cudaFuncAttributeMaxDynamicSharedMemorySize,
                             ATTN_SMEM_FLOATS * 4);
        attr_done = 1;
    }

    gemm_bias_kernel<1><<<dim3(29, 4), 256>>>(query, Wq, bq, pqT, BB * NQQ,
                                              NQQ, QSCALE_F * LOG2E_F);
    gemm_bias_kernel<1><<<dim3(128, 4), 256>>>(key, Wk, bk, pkT, BB * HWK,
                                               HWK, 1.0f);
    gemm_bias_kernel<0><<<dim3(128, 4), 256>>>(value, Wv, bv, pv, BB * HWK,
                                               HWK, 1.0f);

    rpe_kernel<<<dim3(225, 2), 256>>>(refp, W1x, b1x, W2x, W1y, b1y, W2y);

    attn_kernel<<<dim3(15, NH, BB * NSPLIT), 128, ATTN_SMEM_FLOATS * 4>>>();

    combine_kernel<<<225, 256>>>(patt);

    gemm_bias_kernel<0><<<dim3(29, 4), 256>>>(patt, Wo, bo, out, BB * NQQ,
                                              NQQ, 1.0f);
}